// round 2
// baseline (speedup 1.0000x reference)
#include <cuda_runtime.h>
#include <cuda_bf16.h>
#include <math.h>

#define N_NODES 100000
#define N_EDGES 1600000
#define IN_CH   128
#define HID     128
#define OUT_CH  64

// ---------------- scratch (device globals; no allocation allowed) ----------
__device__ float g_h[(size_t)N_NODES * HID];      // transformed + src-scaled features
__device__ float g_agg[(size_t)N_NODES * HID];    // aggregated / activated output
__device__ float g_dinv[N_NODES];
__device__ int   g_deg[N_NODES];
__device__ int   g_rowptr[N_NODES + 1];
__device__ int   g_cursor[N_NODES];
__device__ int   g_csr[N_EDGES];
#define POOL_BLOCKS 240
__device__ float g_partial[POOL_BLOCKS * OUT_CH];

// ---------------- CSR build ------------------------------------------------
__global__ void zero_deg_kernel() {
    int i = blockIdx.x * blockDim.x + threadIdx.x;
    if (i < N_NODES) g_deg[i] = 0;
}

__global__ void count_deg_kernel(const int* __restrict__ ei) {
    int e = blockIdx.x * blockDim.x + threadIdx.x;
    if (e < N_EDGES) atomicAdd(&g_deg[ei[N_EDGES + e]], 1);
}

__global__ void dinv_kernel() {
    int i = blockIdx.x * blockDim.x + threadIdx.x;
    if (i < N_NODES) g_dinv[i] = rsqrtf((float)(g_deg[i] + 1));  // +1 self-loop
}

// single-block exclusive scan over g_deg -> g_rowptr, g_cursor
__global__ void scan_kernel() {
    __shared__ int partial[1024];
    const int t = threadIdx.x;
    const int chunk = (N_NODES + 1023) / 1024;  // 98
    int start = t * chunk;
    int end = start + chunk; if (end > N_NODES) end = N_NODES;
    if (start > N_NODES) start = N_NODES;

    int s = 0;
    for (int i = start; i < end; i++) s += g_deg[i];
    partial[t] = s;
    __syncthreads();
    // Hillis-Steele inclusive scan
    for (int off = 1; off < 1024; off <<= 1) {
        int v = 0;
        if (t >= off) v = partial[t - off];
        __syncthreads();
        if (t >= off) partial[t] += v;
        __syncthreads();
    }
    int pre = (t == 0) ? 0 : partial[t - 1];
    for (int i = start; i < end; i++) {
        g_rowptr[i] = pre;
        g_cursor[i] = pre;
        pre += g_deg[i];
    }
    if (t == 1023) g_rowptr[N_NODES] = pre;  // == total edges
}

__global__ void fill_csr_kernel(const int* __restrict__ ei) {
    int e = blockIdx.x * blockDim.x + threadIdx.x;
    if (e < N_EDGES) {
        int dst = ei[N_EDGES + e];
        int pos = atomicAdd(&g_cursor[dst], 1);
        g_csr[pos] = ei[e];
    }
}

// ---------------- GEMM: out[m][n] = dinv[m] * sum_k A[m][k]*W[k][n] ---------
// K = 128 fixed. BM=128, BK=16, 8x8 micro-tile.
template <int BN>
__global__ void gemm_scale_kernel(const float* __restrict__ A,
                                  const float* __restrict__ W,
                                  float* __restrict__ out, int M) {
    constexpr int BM = 128, BK = 16;
    constexpr int TX = BN / 8;       // 16 or 8
    constexpr int NT = TX * (BM / 8);

    __shared__ float As[BK][BM];     // transposed: As[k][m]
    __shared__ float Bs[BK][BN];

    const int tid = threadIdx.x;
    const int tx = tid % TX, ty = tid / TX;
    const int m0 = blockIdx.x * BM;

    float acc[8][8];
#pragma unroll
    for (int i = 0; i < 8; i++)
#pragma unroll
        for (int j = 0; j < 8; j++) acc[i][j] = 0.f;

    for (int k0 = 0; k0 < 128; k0 += BK) {
        // A tile: BM x BK, stored transposed
#pragma unroll
        for (int i = tid; i < BM * BK / 4; i += NT) {
            int m = i / (BK / 4);
            int kk4 = (i % (BK / 4)) * 4;
            int row = m0 + m;
            float4 v = make_float4(0.f, 0.f, 0.f, 0.f);
            if (row < M)
                v = *reinterpret_cast<const float4*>(&A[(size_t)row * 128 + k0 + kk4]);
            As[kk4 + 0][m] = v.x;
            As[kk4 + 1][m] = v.y;
            As[kk4 + 2][m] = v.z;
            As[kk4 + 3][m] = v.w;
        }
        // B tile: BK x BN
#pragma unroll
        for (int i = tid; i < BK * BN / 4; i += NT) {
            int kk = i / (BN / 4);
            int n4 = (i % (BN / 4)) * 4;
            *reinterpret_cast<float4*>(&Bs[kk][n4]) =
                *reinterpret_cast<const float4*>(&W[(size_t)(k0 + kk) * BN + n4]);
        }
        __syncthreads();

#pragma unroll
        for (int kk = 0; kk < BK; kk++) {
            float a[8], b[8];
            *reinterpret_cast<float4*>(&a[0]) = *reinterpret_cast<float4*>(&As[kk][ty * 8]);
            *reinterpret_cast<float4*>(&a[4]) = *reinterpret_cast<float4*>(&As[kk][ty * 8 + 4]);
            *reinterpret_cast<float4*>(&b[0]) = *reinterpret_cast<float4*>(&Bs[kk][tx * 8]);
            *reinterpret_cast<float4*>(&b[4]) = *reinterpret_cast<float4*>(&Bs[kk][tx * 8 + 4]);
#pragma unroll
            for (int i = 0; i < 8; i++)
#pragma unroll
                for (int j = 0; j < 8; j++) acc[i][j] += a[i] * b[j];
        }
        __syncthreads();
    }

#pragma unroll
    for (int i = 0; i < 8; i++) {
        int row = m0 + ty * 8 + i;
        if (row < M) {
            float d = g_dinv[row];
#pragma unroll
            for (int j4 = 0; j4 < 8; j4 += 4) {
                float4 v;
                v.x = acc[i][j4 + 0] * d;
                v.y = acc[i][j4 + 1] * d;
                v.z = acc[i][j4 + 2] * d;
                v.w = acc[i][j4 + 3] * d;
                *reinterpret_cast<float4*>(&out[(size_t)row * BN + tx * 8 + j4]) = v;
            }
        }
    }
}

// ---------------- SpMM (warp per dst node) ----------------------------------
// out[i] = act( dinv[i] * (h[i] + sum_{src in csr row i} h[src]) + bias )
template <int C, bool RELU>
__global__ void spmm_kernel(const float* __restrict__ h,
                            const float* __restrict__ bias,
                            float* __restrict__ out) {
    constexpr int V = C / 32;  // floats per lane (4 or 2)
    int gw = (blockIdx.x * blockDim.x + threadIdx.x) >> 5;
    int lane = threadIdx.x & 31;
    if (gw >= N_NODES) return;

    int beg = g_rowptr[gw];
    int end = g_rowptr[gw + 1];

    float acc[V];
    // self loop
    {
        const float* hp = &h[(size_t)gw * C + lane * V];
        if (V == 4) {
            float4 v = *reinterpret_cast<const float4*>(hp);
            acc[0] = v.x; acc[1] = v.y; acc[2] = v.z; acc[3] = v.w;
        } else {
            float2 v = *reinterpret_cast<const float2*>(hp);
            acc[0] = v.x; acc[1] = v.y;
        }
    }

    int j = beg;
    for (; j + 1 < end; j += 2) {
        int s0 = g_csr[j];
        int s1 = g_csr[j + 1];
        if (V == 4) {
            float4 v0 = *reinterpret_cast<const float4*>(&h[(size_t)s0 * C + lane * 4]);
            float4 v1 = *reinterpret_cast<const float4*>(&h[(size_t)s1 * C + lane * 4]);
            acc[0] += v0.x + v1.x; acc[1] += v0.y + v1.y;
            acc[2] += v0.z + v1.z; acc[3] += v0.w + v1.w;
        } else {
            float2 v0 = *reinterpret_cast<const float2*>(&h[(size_t)s0 * C + lane * 2]);
            float2 v1 = *reinterpret_cast<const float2*>(&h[(size_t)s1 * C + lane * 2]);
            acc[0] += v0.x + v1.x; acc[1] += v0.y + v1.y;
        }
    }
    if (j < end) {
        int s0 = g_csr[j];
        if (V == 4) {
            float4 v0 = *reinterpret_cast<const float4*>(&h[(size_t)s0 * C + lane * 4]);
            acc[0] += v0.x; acc[1] += v0.y; acc[2] += v0.z; acc[3] += v0.w;
        } else {
            float2 v0 = *reinterpret_cast<const float2*>(&h[(size_t)s0 * C + lane * 2]);
            acc[0] += v0.x; acc[1] += v0.y;
        }
    }

    float d = g_dinv[gw];
#pragma unroll
    for (int v = 0; v < V; v++) {
        float val = acc[v] * d + bias[lane * V + v];
        if (RELU) val = fmaxf(val, 0.f);
        acc[v] = val;
    }
    if (V == 4) {
        float4 o = make_float4(acc[0], acc[1], acc[2], acc[3]);
        *reinterpret_cast<float4*>(&out[(size_t)gw * C + lane * 4]) = o;
    } else {
        float2 o = make_float2(acc[0], acc[1]);
        *reinterpret_cast<float2*>(&out[(size_t)gw * C + lane * 2]) = o;
    }
}

// ---------------- min pool --------------------------------------------------
__global__ void min_part_kernel(const float* __restrict__ g) {
    int c = threadIdx.x & 63;
    int r = threadIdx.x >> 6;  // 0..3
    float m = 3.4028235e38f;
    for (int row = blockIdx.x * 4 + r; row < N_NODES; row += gridDim.x * 4)
        m = fminf(m, g[(size_t)row * OUT_CH + c]);
    __shared__ float sm[256];
    sm[threadIdx.x] = m;
    __syncthreads();
    if (threadIdx.x < 128) sm[threadIdx.x] = fminf(sm[threadIdx.x], sm[threadIdx.x + 128]);
    __syncthreads();
    if (threadIdx.x < 64)
        g_partial[blockIdx.x * OUT_CH + threadIdx.x] =
            fminf(sm[threadIdx.x], sm[threadIdx.x + 64]);
}

__global__ void min_final_kernel(float* __restrict__ out) {
    int c = threadIdx.x;  // 64
    float m = 3.4028235e38f;
    for (int b = 0; b < POOL_BLOCKS; b++) m = fminf(m, g_partial[b * OUT_CH + c]);
    out[c] = m;
}

// ---------------- launch ----------------------------------------------------
extern "C" void kernel_launch(void* const* d_in, const int* in_sizes, int n_in,
                              void* d_out, int out_size) {
    const float* x  = (const float*)d_in[0];
    const int*   ei = (const int*)  d_in[1];
    const float* W1 = (const float*)d_in[2];
    const float* b1 = (const float*)d_in[3];
    const float* W2 = (const float*)d_in[4];
    const float* b2 = (const float*)d_in[5];
    const float* W3 = (const float*)d_in[6];
    const float* b3 = (const float*)d_in[7];
    float* out = (float*)d_out;

    float *h_ptr = nullptr, *agg_ptr = nullptr;
    cudaGetSymbolAddress((void**)&h_ptr, g_h);
    cudaGetSymbolAddress((void**)&agg_ptr, g_agg);

    const int TPB = 256;
    // CSR build
    zero_deg_kernel<<<(N_NODES + TPB - 1) / TPB, TPB>>>();
    count_deg_kernel<<<(N_EDGES + TPB - 1) / TPB, TPB>>>(ei);
    dinv_kernel<<<(N_NODES + TPB - 1) / TPB, TPB>>>();
    scan_kernel<<<1, 1024>>>();
    fill_csr_kernel<<<(N_EDGES + TPB - 1) / TPB, TPB>>>(ei);

    const int gemm_blocks = (N_NODES + 127) / 128;
    const int spmm_blocks = (N_NODES * 32 + TPB - 1) / TPB;

    // Layer 1: h = (x @ W1) * dinv ; agg = relu(dinv*(agg_sum) + b1)
    gemm_scale_kernel<128><<<gemm_blocks, 256>>>(x, W1, h_ptr, N_NODES);
    spmm_kernel<128, true><<<spmm_blocks, TPB>>>(h_ptr, b1, agg_ptr);

    // Layer 2
    gemm_scale_kernel<128><<<gemm_blocks, 256>>>(agg_ptr, W2, h_ptr, N_NODES);
    spmm_kernel<128, true><<<spmm_blocks, TPB>>>(h_ptr, b2, agg_ptr);

    // Layer 3 (no relu, 64 out channels)
    gemm_scale_kernel<64><<<gemm_blocks, 128>>>(agg_ptr, W3, h_ptr, N_NODES);
    spmm_kernel<64, false><<<spmm_blocks, TPB>>>(h_ptr, b3, agg_ptr);

    // min pool
    min_part_kernel<<<POOL_BLOCKS, 256>>>(agg_ptr);
    min_final_kernel<<<1, 64>>>(out);
}

// round 3
// speedup vs baseline: 1.3370x; 1.3370x over previous
#include <cuda_runtime.h>
#include <cuda_bf16.h>
#include <math.h>

#define N_NODES 100000
#define N_EDGES 1600000
#define IN_CH   128
#define HID     128
#define OUT_CH  64

#define SCAN_NBLK ((N_NODES + 255) / 256)   // 391

// ---------------- scratch (device globals; no allocation allowed) ----------
__device__ float g_h[(size_t)N_NODES * HID];      // transformed + src-scaled features
__device__ float g_agg[(size_t)N_NODES * HID];    // aggregated / activated output
__device__ float g_dinv[N_NODES];
__device__ int   g_deg[N_NODES];
__device__ int   g_rowptr[N_NODES + 1];
__device__ int   g_cursor[N_NODES];
__device__ int   g_csr[N_EDGES];
__device__ int   g_bsum[SCAN_NBLK];
__device__ int   g_boff[SCAN_NBLK];
#define POOL_BLOCKS 240
__device__ float g_partial[POOL_BLOCKS * OUT_CH];

// ---------------- CSR build ------------------------------------------------
__global__ void zero_deg_kernel() {
    int i = blockIdx.x * blockDim.x + threadIdx.x;
    if (i < N_NODES) g_deg[i] = 0;
}

__global__ void count_deg_kernel(const int* __restrict__ ei) {
    int e = blockIdx.x * blockDim.x + threadIdx.x;
    if (e < N_EDGES) atomicAdd(&g_deg[ei[N_EDGES + e]], 1);
}

// ---- multi-block exclusive scan of g_deg -> g_rowptr / g_cursor (+dinv) ----
__global__ void scan_pass1() {
    int i = blockIdx.x * 256 + threadIdx.x;
    int d = (i < N_NODES) ? g_deg[i] : 0;
    __shared__ int sm[256];
    sm[threadIdx.x] = d;
    __syncthreads();
#pragma unroll
    for (int o = 128; o > 0; o >>= 1) {
        if (threadIdx.x < o) sm[threadIdx.x] += sm[threadIdx.x + o];
        __syncthreads();
    }
    if (threadIdx.x == 0) g_bsum[blockIdx.x] = sm[0];
}

__global__ void scan_pass2() {
    __shared__ int sm[512];
    int t = threadIdx.x;
    sm[t] = (t < SCAN_NBLK) ? g_bsum[t] : 0;
    __syncthreads();
    for (int o = 1; o < 512; o <<= 1) {
        int v = (t >= o) ? sm[t - o] : 0;
        __syncthreads();
        sm[t] += v;
        __syncthreads();
    }
    if (t < SCAN_NBLK) g_boff[t] = (t == 0) ? 0 : sm[t - 1];
    if (t == 511) g_rowptr[N_NODES] = sm[SCAN_NBLK - 1];
}

__global__ void scan_pass3() {
    int i = blockIdx.x * 256 + threadIdx.x;
    int d = (i < N_NODES) ? g_deg[i] : 0;
    __shared__ int sm[256];
    int t = threadIdx.x;
    sm[t] = d;
    __syncthreads();
    for (int o = 1; o < 256; o <<= 1) {
        int v = (t >= o) ? sm[t - o] : 0;
        __syncthreads();
        sm[t] += v;
        __syncthreads();
    }
    if (i < N_NODES) {
        int excl = g_boff[blockIdx.x] + sm[t] - d;
        g_rowptr[i] = excl;
        g_cursor[i] = excl;
        g_dinv[i] = rsqrtf((float)(d + 1));  // +1 self-loop
    }
}

__global__ void fill_csr_kernel(const int* __restrict__ ei) {
    int e = blockIdx.x * blockDim.x + threadIdx.x;
    if (e < N_EDGES) {
        int dst = ei[N_EDGES + e];
        int pos = atomicAdd(&g_cursor[dst], 1);
        g_csr[pos] = ei[e];
    }
}

// ---------------- GEMM: out[m][n] = dinv[m] * sum_k A[m][k]*W[k][n] ---------
// K = 128 fixed. BM=128, BK=16, 8x8 micro-tile.
template <int BN>
__global__ void gemm_scale_kernel(const float* __restrict__ A,
                                  const float* __restrict__ W,
                                  float* __restrict__ out, int M) {
    constexpr int BM = 128, BK = 16;
    constexpr int TX = BN / 8;       // 16 or 8
    constexpr int NT = TX * (BM / 8);

    __shared__ float As[BK][BM];     // transposed: As[k][m]
    __shared__ float Bs[BK][BN];

    const int tid = threadIdx.x;
    const int tx = tid % TX, ty = tid / TX;
    const int m0 = blockIdx.x * BM;

    float acc[8][8];
#pragma unroll
    for (int i = 0; i < 8; i++)
#pragma unroll
        for (int j = 0; j < 8; j++) acc[i][j] = 0.f;

    for (int k0 = 0; k0 < 128; k0 += BK) {
#pragma unroll
        for (int i = tid; i < BM * BK / 4; i += NT) {
            int m = i / (BK / 4);
            int kk4 = (i % (BK / 4)) * 4;
            int row = m0 + m;
            float4 v = make_float4(0.f, 0.f, 0.f, 0.f);
            if (row < M)
                v = *reinterpret_cast<const float4*>(&A[(size_t)row * 128 + k0 + kk4]);
            As[kk4 + 0][m] = v.x;
            As[kk4 + 1][m] = v.y;
            As[kk4 + 2][m] = v.z;
            As[kk4 + 3][m] = v.w;
        }
#pragma unroll
        for (int i = tid; i < BK * BN / 4; i += NT) {
            int kk = i / (BN / 4);
            int n4 = (i % (BN / 4)) * 4;
            *reinterpret_cast<float4*>(&Bs[kk][n4]) =
                *reinterpret_cast<const float4*>(&W[(size_t)(k0 + kk) * BN + n4]);
        }
        __syncthreads();

#pragma unroll
        for (int kk = 0; kk < BK; kk++) {
            float a[8], b[8];
            *reinterpret_cast<float4*>(&a[0]) = *reinterpret_cast<float4*>(&As[kk][ty * 8]);
            *reinterpret_cast<float4*>(&a[4]) = *reinterpret_cast<float4*>(&As[kk][ty * 8 + 4]);
            *reinterpret_cast<float4*>(&b[0]) = *reinterpret_cast<float4*>(&Bs[kk][tx * 8]);
            *reinterpret_cast<float4*>(&b[4]) = *reinterpret_cast<float4*>(&Bs[kk][tx * 8 + 4]);
#pragma unroll
            for (int i = 0; i < 8; i++)
#pragma unroll
                for (int j = 0; j < 8; j++) acc[i][j] += a[i] * b[j];
        }
        __syncthreads();
    }

#pragma unroll
    for (int i = 0; i < 8; i++) {
        int row = m0 + ty * 8 + i;
        if (row < M) {
            float d = g_dinv[row];
#pragma unroll
            for (int j4 = 0; j4 < 8; j4 += 4) {
                float4 v;
                v.x = acc[i][j4 + 0] * d;
                v.y = acc[i][j4 + 1] * d;
                v.z = acc[i][j4 + 2] * d;
                v.w = acc[i][j4 + 3] * d;
                *reinterpret_cast<float4*>(&out[(size_t)row * BN + tx * 8 + j4]) = v;
            }
        }
    }
}

// ---------------- SpMM (warp per dst node, 4-edge unrolled) -----------------
// out[i] = act( dinv[i] * (h[i] + sum_{src in csr row i} h[src]) + bias )
template <int C, bool RELU>
__global__ void spmm_kernel(const float* __restrict__ h,
                            const float* __restrict__ bias,
                            float* __restrict__ out) {
    constexpr int V = C / 32;  // floats per lane (4 or 2)
    int gw = (blockIdx.x * blockDim.x + threadIdx.x) >> 5;
    int lane = threadIdx.x & 31;
    if (gw >= N_NODES) return;

    int beg = g_rowptr[gw];
    int end = g_rowptr[gw + 1];

    float acc[V];
    // self loop
    {
        const float* hp = &h[(size_t)gw * C + lane * V];
        if (V == 4) {
            float4 v = *reinterpret_cast<const float4*>(hp);
            acc[0] = v.x; acc[1] = v.y; acc[2] = v.z; acc[3] = v.w;
        } else {
            float2 v = *reinterpret_cast<const float2*>(hp);
            acc[0] = v.x; acc[1] = v.y;
        }
    }

    int j = beg;
    for (; j + 3 < end; j += 4) {
        int s0 = g_csr[j];
        int s1 = g_csr[j + 1];
        int s2 = g_csr[j + 2];
        int s3 = g_csr[j + 3];
        if (V == 4) {
            float4 v0 = *reinterpret_cast<const float4*>(&h[(size_t)s0 * C + lane * 4]);
            float4 v1 = *reinterpret_cast<const float4*>(&h[(size_t)s1 * C + lane * 4]);
            float4 v2 = *reinterpret_cast<const float4*>(&h[(size_t)s2 * C + lane * 4]);
            float4 v3 = *reinterpret_cast<const float4*>(&h[(size_t)s3 * C + lane * 4]);
            acc[0] += (v0.x + v1.x) + (v2.x + v3.x);
            acc[1] += (v0.y + v1.y) + (v2.y + v3.y);
            acc[2] += (v0.z + v1.z) + (v2.z + v3.z);
            acc[3] += (v0.w + v1.w) + (v2.w + v3.w);
        } else {
            float2 v0 = *reinterpret_cast<const float2*>(&h[(size_t)s0 * C + lane * 2]);
            float2 v1 = *reinterpret_cast<const float2*>(&h[(size_t)s1 * C + lane * 2]);
            float2 v2 = *reinterpret_cast<const float2*>(&h[(size_t)s2 * C + lane * 2]);
            float2 v3 = *reinterpret_cast<const float2*>(&h[(size_t)s3 * C + lane * 2]);
            acc[0] += (v0.x + v1.x) + (v2.x + v3.x);
            acc[1] += (v0.y + v1.y) + (v2.y + v3.y);
        }
    }
    for (; j < end; j++) {
        int s0 = g_csr[j];
        if (V == 4) {
            float4 v0 = *reinterpret_cast<const float4*>(&h[(size_t)s0 * C + lane * 4]);
            acc[0] += v0.x; acc[1] += v0.y; acc[2] += v0.z; acc[3] += v0.w;
        } else {
            float2 v0 = *reinterpret_cast<const float2*>(&h[(size_t)s0 * C + lane * 2]);
            acc[0] += v0.x; acc[1] += v0.y;
        }
    }

    float d = g_dinv[gw];
#pragma unroll
    for (int v = 0; v < V; v++) {
        float val = acc[v] * d + bias[lane * V + v];
        if (RELU) val = fmaxf(val, 0.f);
        acc[v] = val;
    }
    if (V == 4) {
        float4 o = make_float4(acc[0], acc[1], acc[2], acc[3]);
        *reinterpret_cast<float4*>(&out[(size_t)gw * C + lane * 4]) = o;
    } else {
        float2 o = make_float2(acc[0], acc[1]);
        *reinterpret_cast<float2*>(&out[(size_t)gw * C + lane * 2]) = o;
    }
}

// ---------------- min pool --------------------------------------------------
__global__ void min_part_kernel(const float* __restrict__ g) {
    int c = threadIdx.x & 63;
    int r = threadIdx.x >> 6;  // 0..3
    float m = 3.4028235e38f;
    for (int row = blockIdx.x * 4 + r; row < N_NODES; row += gridDim.x * 4)
        m = fminf(m, g[(size_t)row * OUT_CH + c]);
    __shared__ float sm[256];
    sm[threadIdx.x] = m;
    __syncthreads();
    if (threadIdx.x < 128) sm[threadIdx.x] = fminf(sm[threadIdx.x], sm[threadIdx.x + 128]);
    __syncthreads();
    if (threadIdx.x < 64)
        g_partial[blockIdx.x * OUT_CH + threadIdx.x] =
            fminf(sm[threadIdx.x], sm[threadIdx.x + 64]);
}

__global__ void min_final_kernel(float* __restrict__ out) {
    int c = threadIdx.x;  // 64
    float m = 3.4028235e38f;
    for (int b = 0; b < POOL_BLOCKS; b++) m = fminf(m, g_partial[b * OUT_CH + c]);
    out[c] = m;
}

// ---------------- launch ----------------------------------------------------
extern "C" void kernel_launch(void* const* d_in, const int* in_sizes, int n_in,
                              void* d_out, int out_size) {
    const float* x  = (const float*)d_in[0];
    const int*   ei = (const int*)  d_in[1];
    const float* W1 = (const float*)d_in[2];
    const float* b1 = (const float*)d_in[3];
    const float* W2 = (const float*)d_in[4];
    const float* b2 = (const float*)d_in[5];
    const float* W3 = (const float*)d_in[6];
    const float* b3 = (const float*)d_in[7];
    float* out = (float*)d_out;

    float *h_ptr = nullptr, *agg_ptr = nullptr;
    cudaGetSymbolAddress((void**)&h_ptr, g_h);
    cudaGetSymbolAddress((void**)&agg_ptr, g_agg);

    const int TPB = 256;
    // CSR build
    zero_deg_kernel<<<(N_NODES + TPB - 1) / TPB, TPB>>>();
    count_deg_kernel<<<(N_EDGES + TPB - 1) / TPB, TPB>>>(ei);
    scan_pass1<<<SCAN_NBLK, 256>>>();
    scan_pass2<<<1, 512>>>();
    scan_pass3<<<SCAN_NBLK, 256>>>();
    fill_csr_kernel<<<(N_EDGES + TPB - 1) / TPB, TPB>>>(ei);

    const int gemm_blocks = (N_NODES + 127) / 128;
    const int spmm_blocks = (N_NODES * 32 + TPB - 1) / TPB;

    // Layer 1: h = (x @ W1) * dinv ; agg = relu(dinv*(agg_sum) + b1)
    gemm_scale_kernel<128><<<gemm_blocks, 256>>>(x, W1, h_ptr, N_NODES);
    spmm_kernel<128, true><<<spmm_blocks, TPB>>>(h_ptr, b1, agg_ptr);

    // Layer 2
    gemm_scale_kernel<128><<<gemm_blocks, 256>>>(agg_ptr, W2, h_ptr, N_NODES);
    spmm_kernel<128, true><<<spmm_blocks, TPB>>>(h_ptr, b2, agg_ptr);

    // Layer 3 (no relu, 64 out channels)
    gemm_scale_kernel<64><<<gemm_blocks, 128>>>(agg_ptr, W3, h_ptr, N_NODES);
    spmm_kernel<64, false><<<spmm_blocks, TPB>>>(h_ptr, b3, agg_ptr);

    // min pool
    min_part_kernel<<<POOL_BLOCKS, 256>>>(agg_ptr);
    min_final_kernel<<<1, 64>>>(out);
}

// round 5
// speedup vs baseline: 1.9097x; 1.4283x over previous
#include <cuda_runtime.h>
#include <cuda_bf16.h>
#include <math.h>
#include <cstdint>

#define N_NODES 100000
#define N_EDGES 1600000
#define IN_CH   128
#define HID     128
#define OUT_CH  64

#define SCAN_NBLK ((N_NODES + 255) / 256)   // 391

// ---------------- scratch (device globals; no allocation allowed) ----------
__device__ float g_h[(size_t)N_NODES * HID];      // transformed + src-scaled features
__device__ float g_agg[(size_t)N_NODES * HID];    // aggregated / activated output
__device__ float g_dinv[N_NODES];
__device__ int   g_deg[N_NODES];
__device__ int   g_rowptr[N_NODES + 1];
__device__ int   g_cursor[N_NODES];
__device__ int   g_csr[N_EDGES];
__device__ int   g_bsum[SCAN_NBLK];
__device__ int   g_boff[SCAN_NBLK];
#define POOL_BLOCKS 240
__device__ float g_partial[POOL_BLOCKS * OUT_CH];

// ---------------- CSR build ------------------------------------------------
__global__ void zero_deg_kernel() {
    int i = blockIdx.x * blockDim.x + threadIdx.x;
    if (i < N_NODES) g_deg[i] = 0;
}

__global__ void count_deg_kernel(const int* __restrict__ ei) {
    int e = blockIdx.x * blockDim.x + threadIdx.x;
    if (e < N_EDGES) atomicAdd(&g_deg[ei[N_EDGES + e]], 1);
}

__global__ void scan_pass1() {
    int i = blockIdx.x * 256 + threadIdx.x;
    int d = (i < N_NODES) ? g_deg[i] : 0;
    __shared__ int sm[256];
    sm[threadIdx.x] = d;
    __syncthreads();
#pragma unroll
    for (int o = 128; o > 0; o >>= 1) {
        if (threadIdx.x < o) sm[threadIdx.x] += sm[threadIdx.x + o];
        __syncthreads();
    }
    if (threadIdx.x == 0) g_bsum[blockIdx.x] = sm[0];
}

__global__ void scan_pass2() {
    __shared__ int sm[512];
    int t = threadIdx.x;
    sm[t] = (t < SCAN_NBLK) ? g_bsum[t] : 0;
    __syncthreads();
    for (int o = 1; o < 512; o <<= 1) {
        int v = (t >= o) ? sm[t - o] : 0;
        __syncthreads();
        sm[t] += v;
        __syncthreads();
    }
    if (t < SCAN_NBLK) g_boff[t] = (t == 0) ? 0 : sm[t - 1];
    if (t == 511) g_rowptr[N_NODES] = sm[SCAN_NBLK - 1];
}

__global__ void scan_pass3() {
    int i = blockIdx.x * 256 + threadIdx.x;
    int d = (i < N_NODES) ? g_deg[i] : 0;
    __shared__ int sm[256];
    int t = threadIdx.x;
    sm[t] = d;
    __syncthreads();
    for (int o = 1; o < 256; o <<= 1) {
        int v = (t >= o) ? sm[t - o] : 0;
        __syncthreads();
        sm[t] += v;
        __syncthreads();
    }
    if (i < N_NODES) {
        int excl = g_boff[blockIdx.x] + sm[t] - d;
        g_rowptr[i] = excl;
        g_cursor[i] = excl;
        g_dinv[i] = rsqrtf((float)(d + 1));  // +1 self-loop
    }
}

__global__ void fill_csr_kernel(const int* __restrict__ ei) {
    int e = blockIdx.x * blockDim.x + threadIdx.x;
    if (e < N_EDGES) {
        int dst = ei[N_EDGES + e];
        int pos = atomicAdd(&g_cursor[dst], 1);
        g_csr[pos] = ei[e];
    }
}

// ---------------- tf32 mma helpers ------------------------------------------
__device__ __forceinline__ uint32_t f2tf32(float f) {
    uint32_t u;
    asm("cvt.rna.tf32.f32 %0, %1;" : "=r"(u) : "f"(f));
    return u;
}

__device__ __forceinline__ void mma_tf32(float* c, const uint32_t* a, const uint32_t* b) {
    asm volatile(
        "mma.sync.aligned.m16n8k8.row.col.f32.tf32.tf32.f32 "
        "{%0,%1,%2,%3}, {%4,%5,%6,%7}, {%8,%9}, {%0,%1,%2,%3};"
        : "+f"(c[0]), "+f"(c[1]), "+f"(c[2]), "+f"(c[3])
        : "r"(a[0]), "r"(a[1]), "r"(a[2]), "r"(a[3]), "r"(b[0]), "r"(b[1]));
}

// ---------------- tensor-core GEMM: out[m][n] = dinv[m] * (A @ W)[m][n] -----
// A: [M,128] row-major fp32. W: [128,BN] row-major fp32. 256 threads/CTA.
// Warp layout: 4 (M) x 2 (N); warp tile = 32 (M) x BN/2 (N); mma m16n8k8 tf32.
template <int BN>
__global__ void __launch_bounds__(256)
gemm_mma_kernel(const float* __restrict__ A, const float* __restrict__ W,
                float* __restrict__ out, int M) {
    constexpr int PAD_A = 132;       // 128 + 4 (bank-conflict-free fragment loads)
    constexpr int PAD_B = BN + 4;
    constexpr int TN = BN / 16;      // n-tiles (of 8) per warp: 8 or 4

    extern __shared__ uint32_t smem[];
    uint32_t* As = smem;                    // [128][PAD_A]
    uint32_t* Bs = smem + 128 * PAD_A;      // [128][PAD_B]  (k-major, = W layout)

    const int tid = threadIdx.x;
    const int lane = tid & 31;
    const int wid = tid >> 5;
    const int wm = (wid & 3) * 32;          // warp M offset in tile
    const int wn = (wid >> 2) * (BN / 2);   // warp N offset
    const int m0 = blockIdx.x * 128;

    // ---- load A tile (tf32-rounded) ----
#pragma unroll
    for (int i = tid; i < 128 * 32; i += 256) {
        int r = i >> 5;
        int c4 = (i & 31) * 4;
        int row = m0 + r;
        float4 v = make_float4(0.f, 0.f, 0.f, 0.f);
        if (row < M)
            v = *reinterpret_cast<const float4*>(&A[(size_t)row * 128 + c4]);
        uint4 u;
        u.x = f2tf32(v.x); u.y = f2tf32(v.y); u.z = f2tf32(v.z); u.w = f2tf32(v.w);
        *reinterpret_cast<uint4*>(&As[r * PAD_A + c4]) = u;
    }
    // ---- load W tile (tf32-rounded) ----
#pragma unroll
    for (int i = tid; i < 128 * (BN / 4); i += 256) {
        int r = i / (BN / 4);
        int c4 = (i % (BN / 4)) * 4;
        float4 v = *reinterpret_cast<const float4*>(&W[(size_t)r * BN + c4]);
        uint4 u;
        u.x = f2tf32(v.x); u.y = f2tf32(v.y); u.z = f2tf32(v.z); u.w = f2tf32(v.w);
        *reinterpret_cast<uint4*>(&Bs[r * PAD_B + c4]) = u;
    }
    __syncthreads();

    float acc[2][TN][4];
#pragma unroll
    for (int mi = 0; mi < 2; mi++)
#pragma unroll
        for (int ni = 0; ni < TN; ni++)
#pragma unroll
            for (int j = 0; j < 4; j++) acc[mi][ni][j] = 0.f;

    const int ar = lane >> 2;      // row-in-tile group
    const int ak = lane & 3;       // k-in-group
    const int bn = wn + (lane >> 2);

#pragma unroll
    for (int k0 = 0; k0 < 128; k0 += 8) {
        uint32_t a[2][4];
#pragma unroll
        for (int mi = 0; mi < 2; mi++) {
            int r = wm + mi * 16 + ar;
            a[mi][0] = As[r * PAD_A + k0 + ak];
            a[mi][1] = As[(r + 8) * PAD_A + k0 + ak];
            a[mi][2] = As[r * PAD_A + k0 + ak + 4];
            a[mi][3] = As[(r + 8) * PAD_A + k0 + ak + 4];
        }
        uint32_t b[TN][2];
#pragma unroll
        for (int ni = 0; ni < TN; ni++) {
            b[ni][0] = Bs[(k0 + ak) * PAD_B + bn + ni * 8];
            b[ni][1] = Bs[(k0 + ak + 4) * PAD_B + bn + ni * 8];
        }
#pragma unroll
        for (int mi = 0; mi < 2; mi++)
#pragma unroll
            for (int ni = 0; ni < TN; ni++)
                mma_tf32(acc[mi][ni], a[mi], b[ni]);
    }

    // ---- epilogue: scale by dinv, store ----
#pragma unroll
    for (int mi = 0; mi < 2; mi++) {
        int r0 = m0 + wm + mi * 16 + (lane >> 2);
        int r1 = r0 + 8;
        float d0 = (r0 < M) ? g_dinv[r0] : 0.f;
        float d1 = (r1 < M) ? g_dinv[r1] : 0.f;
#pragma unroll
        for (int ni = 0; ni < TN; ni++) {
            int col = wn + ni * 8 + (lane & 3) * 2;
            if (r0 < M) {
                float2 v0 = make_float2(acc[mi][ni][0] * d0, acc[mi][ni][1] * d0);
                *reinterpret_cast<float2*>(&out[(size_t)r0 * BN + col]) = v0;
            }
            if (r1 < M) {
                float2 v1 = make_float2(acc[mi][ni][2] * d1, acc[mi][ni][3] * d1);
                *reinterpret_cast<float2*>(&out[(size_t)r1 * BN + col]) = v1;
            }
        }
    }
}

// ---------------- SpMM (warp per dst node, 4-edge unrolled) -----------------
template <int C, bool RELU>
__global__ void spmm_kernel(const float* __restrict__ h,
                            const float* __restrict__ bias,
                            float* __restrict__ out) {
    constexpr int V = C / 32;  // floats per lane (4 or 2)
    int gw = (blockIdx.x * blockDim.x + threadIdx.x) >> 5;
    int lane = threadIdx.x & 31;
    if (gw >= N_NODES) return;

    int beg = g_rowptr[gw];
    int end = g_rowptr[gw + 1];

    float acc[V];
    {
        const float* hp = &h[(size_t)gw * C + lane * V];
        if (V == 4) {
            float4 v = *reinterpret_cast<const float4*>(hp);
            acc[0] = v.x; acc[1] = v.y; acc[2] = v.z; acc[3] = v.w;
        } else {
            float2 v = *reinterpret_cast<const float2*>(hp);
            acc[0] = v.x; acc[1] = v.y;
        }
    }

    int j = beg;
    for (; j + 3 < end; j += 4) {
        int s0 = g_csr[j];
        int s1 = g_csr[j + 1];
        int s2 = g_csr[j + 2];
        int s3 = g_csr[j + 3];
        if (V == 4) {
            float4 v0 = *reinterpret_cast<const float4*>(&h[(size_t)s0 * C + lane * 4]);
            float4 v1 = *reinterpret_cast<const float4*>(&h[(size_t)s1 * C + lane * 4]);
            float4 v2 = *reinterpret_cast<const float4*>(&h[(size_t)s2 * C + lane * 4]);
            float4 v3 = *reinterpret_cast<const float4*>(&h[(size_t)s3 * C + lane * 4]);
            acc[0] += (v0.x + v1.x) + (v2.x + v3.x);
            acc[1] += (v0.y + v1.y) + (v2.y + v3.y);
            acc[2] += (v0.z + v1.z) + (v2.z + v3.z);
            acc[3] += (v0.w + v1.w) + (v2.w + v3.w);
        } else {
            float2 v0 = *reinterpret_cast<const float2*>(&h[(size_t)s0 * C + lane * 2]);
            float2 v1 = *reinterpret_cast<const float2*>(&h[(size_t)s1 * C + lane * 2]);
            float2 v2 = *reinterpret_cast<const float2*>(&h[(size_t)s2 * C + lane * 2]);
            float2 v3 = *reinterpret_cast<const float2*>(&h[(size_t)s3 * C + lane * 2]);
            acc[0] += (v0.x + v1.x) + (v2.x + v3.x);
            acc[1] += (v0.y + v1.y) + (v2.y + v3.y);
        }
    }
    for (; j < end; j++) {
        int s0 = g_csr[j];
        if (V == 4) {
            float4 v0 = *reinterpret_cast<const float4*>(&h[(size_t)s0 * C + lane * 4]);
            acc[0] += v0.x; acc[1] += v0.y; acc[2] += v0.z; acc[3] += v0.w;
        } else {
            float2 v0 = *reinterpret_cast<const float2*>(&h[(size_t)s0 * C + lane * 2]);
            acc[0] += v0.x; acc[1] += v0.y;
        }
    }

    float d = g_dinv[gw];
#pragma unroll
    for (int v = 0; v < V; v++) {
        float val = acc[v] * d + bias[lane * V + v];
        if (RELU) val = fmaxf(val, 0.f);
        acc[v] = val;
    }
    if (V == 4) {
        float4 o = make_float4(acc[0], acc[1], acc[2], acc[3]);
        *reinterpret_cast<float4*>(&out[(size_t)gw * C + lane * 4]) = o;
    } else {
        float2 o = make_float2(acc[0], acc[1]);
        *reinterpret_cast<float2*>(&out[(size_t)gw * C + lane * 2]) = o;
    }
}

// ---------------- min pool --------------------------------------------------
__global__ void min_part_kernel(const float* __restrict__ g) {
    int c = threadIdx.x & 63;
    int r = threadIdx.x >> 6;  // 0..3
    float m = 3.4028235e38f;
    for (int row = blockIdx.x * 4 + r; row < N_NODES; row += gridDim.x * 4)
        m = fminf(m, g[(size_t)row * OUT_CH + c]);
    __shared__ float sm[256];
    sm[threadIdx.x] = m;
    __syncthreads();
    if (threadIdx.x < 128) sm[threadIdx.x] = fminf(sm[threadIdx.x], sm[threadIdx.x + 128]);
    __syncthreads();
    if (threadIdx.x < 64)
        g_partial[blockIdx.x * OUT_CH + threadIdx.x] =
            fminf(sm[threadIdx.x], sm[threadIdx.x + 64]);
}

__global__ void min_final_kernel(float* __restrict__ out) {
    int c = threadIdx.x;  // 64
    float m = 3.4028235e38f;
    for (int b = 0; b < POOL_BLOCKS; b++) m = fminf(m, g_partial[b * OUT_CH + c]);
    out[c] = m;
}

// ---------------- launch ----------------------------------------------------
extern "C" void kernel_launch(void* const* d_in, const int* in_sizes, int n_in,
                              void* d_out, int out_size) {
    const float* x  = (const float*)d_in[0];
    const int*   ei = (const int*)  d_in[1];
    const float* W1 = (const float*)d_in[2];
    const float* b1 = (const float*)d_in[3];
    const float* W2 = (const float*)d_in[4];
    const float* b2 = (const float*)d_in[5];
    const float* W3 = (const float*)d_in[6];
    const float* b3 = (const float*)d_in[7];
    float* out = (float*)d_out;

    float *h_ptr = nullptr, *agg_ptr = nullptr;
    cudaGetSymbolAddress((void**)&h_ptr, g_h);
    cudaGetSymbolAddress((void**)&agg_ptr, g_agg);

    const int SMEM_128 = (128 * 132 + 128 * 132) * 4;  // 135168
    const int SMEM_64  = (128 * 132 + 128 * 68) * 4;   // 102400
    cudaFuncSetAttribute(gemm_mma_kernel<128>,
                         cudaFuncAttributeMaxDynamicSharedMemorySize, SMEM_128);
    cudaFuncSetAttribute(gemm_mma_kernel<64>,
                         cudaFuncAttributeMaxDynamicSharedMemorySize, SMEM_64);

    const int TPB = 256;
    // CSR build
    zero_deg_kernel<<<(N_NODES + TPB - 1) / TPB, TPB>>>();
    count_deg_kernel<<<(N_EDGES + TPB - 1) / TPB, TPB>>>(ei);
    scan_pass1<<<SCAN_NBLK, 256>>>();
    scan_pass2<<<1, 512>>>();
    scan_pass3<<<SCAN_NBLK, 256>>>();
    fill_csr_kernel<<<(N_EDGES + TPB - 1) / TPB, TPB>>>(ei);

    const int gemm_blocks = (N_NODES + 127) / 128;  // 782
    const int spmm_blocks = (N_NODES * 32 + TPB - 1) / TPB;

    // Layer 1
    gemm_mma_kernel<128><<<gemm_blocks, 256, SMEM_128>>>(x, W1, h_ptr, N_NODES);
    spmm_kernel<128, true><<<spmm_blocks, TPB>>>(h_ptr, b1, agg_ptr);

    // Layer 2
    gemm_mma_kernel<128><<<gemm_blocks, 256, SMEM_128>>>(agg_ptr, W2, h_ptr, N_NODES);
    spmm_kernel<128, true><<<spmm_blocks, TPB>>>(h_ptr, b2, agg_ptr);

    // Layer 3 (64 out channels, no relu)
    gemm_mma_kernel<64><<<gemm_blocks, 256, SMEM_64>>>(agg_ptr, W3, h_ptr, N_NODES);
    spmm_kernel<64, false><<<spmm_blocks, TPB>>>(h_ptr, b3, agg_ptr);

    // min pool
    min_part_kernel<<<POOL_BLOCKS, 256>>>(agg_ptr);
    min_final_kernel<<<1, 64>>>(out);
}

// round 6
// speedup vs baseline: 2.0912x; 1.0950x over previous
#include <cuda_runtime.h>
#include <cuda_bf16.h>
#include <math.h>
#include <cstdint>

#define N_NODES 100000
#define N_EDGES 1600000
#define IN_CH   128
#define HID     128
#define OUT_CH  64

#define SCAN_NBLK ((N_NODES + 255) / 256)   // 391

// ---------------- scratch (device globals; no allocation allowed) ----------
__device__ __nv_bfloat16 g_hb[(size_t)N_NODES * HID];  // transformed + src-scaled (bf16)
__device__ float g_agg[(size_t)N_NODES * HID];         // aggregated / activated (fp32)
__device__ float g_dinv[N_NODES];
__device__ int   g_deg[N_NODES];
__device__ int   g_rowptr[N_NODES + 1];
__device__ int   g_cursor[N_NODES];
__device__ int   g_csr[N_EDGES];
__device__ int   g_bsum[SCAN_NBLK];
__device__ int   g_boff[SCAN_NBLK];
#define POOL_BLOCKS 240
__device__ float g_partial[POOL_BLOCKS * OUT_CH];

// ---------------- CSR build ------------------------------------------------
__global__ void zero_deg_kernel() {
    int i = blockIdx.x * blockDim.x + threadIdx.x;
    if (i < N_NODES) g_deg[i] = 0;
}

__global__ void count_deg_kernel(const int* __restrict__ ei) {
    int e = blockIdx.x * blockDim.x + threadIdx.x;
    if (e < N_EDGES) atomicAdd(&g_deg[ei[N_EDGES + e]], 1);
}

__global__ void scan_pass1() {
    int i = blockIdx.x * 256 + threadIdx.x;
    int d = (i < N_NODES) ? g_deg[i] : 0;
    __shared__ int sm[256];
    sm[threadIdx.x] = d;
    __syncthreads();
#pragma unroll
    for (int o = 128; o > 0; o >>= 1) {
        if (threadIdx.x < o) sm[threadIdx.x] += sm[threadIdx.x + o];
        __syncthreads();
    }
    if (threadIdx.x == 0) g_bsum[blockIdx.x] = sm[0];
}

__global__ void scan_pass2() {
    __shared__ int sm[512];
    int t = threadIdx.x;
    sm[t] = (t < SCAN_NBLK) ? g_bsum[t] : 0;
    __syncthreads();
    for (int o = 1; o < 512; o <<= 1) {
        int v = (t >= o) ? sm[t - o] : 0;
        __syncthreads();
        sm[t] += v;
        __syncthreads();
    }
    if (t < SCAN_NBLK) g_boff[t] = (t == 0) ? 0 : sm[t - 1];
    if (t == 511) g_rowptr[N_NODES] = sm[SCAN_NBLK - 1];
}

__global__ void scan_pass3() {
    int i = blockIdx.x * 256 + threadIdx.x;
    int d = (i < N_NODES) ? g_deg[i] : 0;
    __shared__ int sm[256];
    int t = threadIdx.x;
    sm[t] = d;
    __syncthreads();
    for (int o = 1; o < 256; o <<= 1) {
        int v = (t >= o) ? sm[t - o] : 0;
        __syncthreads();
        sm[t] += v;
        __syncthreads();
    }
    if (i < N_NODES) {
        int excl = g_boff[blockIdx.x] + sm[t] - d;
        g_rowptr[i] = excl;
        g_cursor[i] = excl;
        g_dinv[i] = rsqrtf((float)(d + 1));  // +1 self-loop
    }
}

__global__ void fill_csr_kernel(const int* __restrict__ ei) {
    int e = blockIdx.x * blockDim.x + threadIdx.x;
    if (e < N_EDGES) {
        int dst = ei[N_EDGES + e];
        int pos = atomicAdd(&g_cursor[dst], 1);
        g_csr[pos] = ei[e];
    }
}

// ---------------- tf32 mma helpers ------------------------------------------
__device__ __forceinline__ uint32_t f2tf32(float f) {
    uint32_t u;
    asm("cvt.rna.tf32.f32 %0, %1;" : "=r"(u) : "f"(f));
    return u;
}

__device__ __forceinline__ void mma_tf32(float* c, const uint32_t* a, const uint32_t* b) {
    asm volatile(
        "mma.sync.aligned.m16n8k8.row.col.f32.tf32.tf32.f32 "
        "{%0,%1,%2,%3}, {%4,%5,%6,%7}, {%8,%9}, {%0,%1,%2,%3};"
        : "+f"(c[0]), "+f"(c[1]), "+f"(c[2]), "+f"(c[3])
        : "r"(a[0]), "r"(a[1]), "r"(a[2]), "r"(a[3]), "r"(b[0]), "r"(b[1]));
}

// ---------------- tensor-core GEMM: outh[m][n] = bf16(dinv[m]*(A@W)[m][n]) --
// A: [M,128] row-major fp32. W: [128,BN] row-major fp32. 256 threads/CTA.
// Warp layout: 4 (M) x 2 (N); warp tile = 32 (M) x BN/2 (N); mma m16n8k8 tf32.
template <int BN>
__global__ void __launch_bounds__(256)
gemm_mma_kernel(const float* __restrict__ A, const float* __restrict__ W,
                __nv_bfloat16* __restrict__ outh, int M) {
    constexpr int PAD_A = 132;       // 128 + 4 (bank-conflict-free fragment loads)
    constexpr int PAD_B = BN + 4;
    constexpr int TN = BN / 16;      // n-tiles (of 8) per warp: 8 or 4

    extern __shared__ uint32_t smem[];
    uint32_t* As = smem;                    // [128][PAD_A]
    uint32_t* Bs = smem + 128 * PAD_A;      // [128][PAD_B]  (k-major, = W layout)

    const int tid = threadIdx.x;
    const int lane = tid & 31;
    const int wid = tid >> 5;
    const int wm = (wid & 3) * 32;          // warp M offset in tile
    const int wn = (wid >> 2) * (BN / 2);   // warp N offset
    const int m0 = blockIdx.x * 128;

    // ---- load A tile (tf32-rounded) ----
#pragma unroll
    for (int i = tid; i < 128 * 32; i += 256) {
        int r = i >> 5;
        int c4 = (i & 31) * 4;
        int row = m0 + r;
        float4 v = make_float4(0.f, 0.f, 0.f, 0.f);
        if (row < M)
            v = *reinterpret_cast<const float4*>(&A[(size_t)row * 128 + c4]);
        uint4 u;
        u.x = f2tf32(v.x); u.y = f2tf32(v.y); u.z = f2tf32(v.z); u.w = f2tf32(v.w);
        *reinterpret_cast<uint4*>(&As[r * PAD_A + c4]) = u;
    }
    // ---- load W tile (tf32-rounded) ----
#pragma unroll
    for (int i = tid; i < 128 * (BN / 4); i += 256) {
        int r = i / (BN / 4);
        int c4 = (i % (BN / 4)) * 4;
        float4 v = *reinterpret_cast<const float4*>(&W[(size_t)r * BN + c4]);
        uint4 u;
        u.x = f2tf32(v.x); u.y = f2tf32(v.y); u.z = f2tf32(v.z); u.w = f2tf32(v.w);
        *reinterpret_cast<uint4*>(&Bs[r * PAD_B + c4]) = u;
    }
    __syncthreads();

    float acc[2][TN][4];
#pragma unroll
    for (int mi = 0; mi < 2; mi++)
#pragma unroll
        for (int ni = 0; ni < TN; ni++)
#pragma unroll
            for (int j = 0; j < 4; j++) acc[mi][ni][j] = 0.f;

    const int ar = lane >> 2;      // row-in-tile group
    const int ak = lane & 3;       // k-in-group
    const int bn = wn + (lane >> 2);

#pragma unroll
    for (int k0 = 0; k0 < 128; k0 += 8) {
        uint32_t a[2][4];
#pragma unroll
        for (int mi = 0; mi < 2; mi++) {
            int r = wm + mi * 16 + ar;
            a[mi][0] = As[r * PAD_A + k0 + ak];
            a[mi][1] = As[(r + 8) * PAD_A + k0 + ak];
            a[mi][2] = As[r * PAD_A + k0 + ak + 4];
            a[mi][3] = As[(r + 8) * PAD_A + k0 + ak + 4];
        }
        uint32_t b[TN][2];
#pragma unroll
        for (int ni = 0; ni < TN; ni++) {
            b[ni][0] = Bs[(k0 + ak) * PAD_B + bn + ni * 8];
            b[ni][1] = Bs[(k0 + ak + 4) * PAD_B + bn + ni * 8];
        }
#pragma unroll
        for (int mi = 0; mi < 2; mi++)
#pragma unroll
            for (int ni = 0; ni < TN; ni++)
                mma_tf32(acc[mi][ni], a[mi], b[ni]);
    }

    // ---- epilogue: scale by dinv, pack bf16x2, store ----
#pragma unroll
    for (int mi = 0; mi < 2; mi++) {
        int r0 = m0 + wm + mi * 16 + (lane >> 2);
        int r1 = r0 + 8;
        float d0 = (r0 < M) ? g_dinv[r0] : 0.f;
        float d1 = (r1 < M) ? g_dinv[r1] : 0.f;
#pragma unroll
        for (int ni = 0; ni < TN; ni++) {
            int col = wn + ni * 8 + (lane & 3) * 2;
            if (r0 < M) {
                __nv_bfloat162 v0 =
                    __floats2bfloat162_rn(acc[mi][ni][0] * d0, acc[mi][ni][1] * d0);
                *reinterpret_cast<__nv_bfloat162*>(&outh[(size_t)r0 * BN + col]) = v0;
            }
            if (r1 < M) {
                __nv_bfloat162 v1 =
                    __floats2bfloat162_rn(acc[mi][ni][2] * d1, acc[mi][ni][3] * d1);
                *reinterpret_cast<__nv_bfloat162*>(&outh[(size_t)r1 * BN + col]) = v1;
            }
        }
    }
}

// ---------------- SpMM (warp per dst node, bf16 gather, fp32 accumulate) ----
// out[i] = act( dinv[i] * (h[i] + sum_{src in csr row i} h[src]) + bias )
template <int C, bool RELU>
__global__ void spmm_kernel(const __nv_bfloat16* __restrict__ h,
                            const float* __restrict__ bias,
                            float* __restrict__ out) {
    constexpr int V = C / 32;       // bf16 per lane: 4 (C=128) or 2 (C=64)
    constexpr int P = V / 2;        // bf16x2 words per lane: 2 or 1
    int gw = (blockIdx.x * blockDim.x + threadIdx.x) >> 5;
    int lane = threadIdx.x & 31;
    if (gw >= N_NODES) return;

    int beg = g_rowptr[gw];
    int end = g_rowptr[gw + 1];

    float2 acc[P];
    // self loop
    {
        const __nv_bfloat162* hp =
            reinterpret_cast<const __nv_bfloat162*>(&h[(size_t)gw * C + lane * V]);
#pragma unroll
        for (int p = 0; p < P; p++) acc[p] = __bfloat1622float2(hp[p]);
    }

    int j = beg;
    for (; j + 3 < end; j += 4) {
        int s0 = g_csr[j];
        int s1 = g_csr[j + 1];
        int s2 = g_csr[j + 2];
        int s3 = g_csr[j + 3];
        const __nv_bfloat162* p0 =
            reinterpret_cast<const __nv_bfloat162*>(&h[(size_t)s0 * C + lane * V]);
        const __nv_bfloat162* p1 =
            reinterpret_cast<const __nv_bfloat162*>(&h[(size_t)s1 * C + lane * V]);
        const __nv_bfloat162* p2 =
            reinterpret_cast<const __nv_bfloat162*>(&h[(size_t)s2 * C + lane * V]);
        const __nv_bfloat162* p3 =
            reinterpret_cast<const __nv_bfloat162*>(&h[(size_t)s3 * C + lane * V]);
#pragma unroll
        for (int p = 0; p < P; p++) {
            float2 v0 = __bfloat1622float2(p0[p]);
            float2 v1 = __bfloat1622float2(p1[p]);
            float2 v2 = __bfloat1622float2(p2[p]);
            float2 v3 = __bfloat1622float2(p3[p]);
            acc[p].x += (v0.x + v1.x) + (v2.x + v3.x);
            acc[p].y += (v0.y + v1.y) + (v2.y + v3.y);
        }
    }
    for (; j < end; j++) {
        int s0 = g_csr[j];
        const __nv_bfloat162* p0 =
            reinterpret_cast<const __nv_bfloat162*>(&h[(size_t)s0 * C + lane * V]);
#pragma unroll
        for (int p = 0; p < P; p++) {
            float2 v0 = __bfloat1622float2(p0[p]);
            acc[p].x += v0.x;
            acc[p].y += v0.y;
        }
    }

    float d = g_dinv[gw];
    float o[V];
#pragma unroll
    for (int p = 0; p < P; p++) {
        float vx = acc[p].x * d + bias[lane * V + p * 2];
        float vy = acc[p].y * d + bias[lane * V + p * 2 + 1];
        if (RELU) { vx = fmaxf(vx, 0.f); vy = fmaxf(vy, 0.f); }
        o[p * 2] = vx; o[p * 2 + 1] = vy;
    }
    if (V == 4) {
        float4 v = make_float4(o[0], o[1], o[2], o[3]);
        *reinterpret_cast<float4*>(&out[(size_t)gw * C + lane * 4]) = v;
    } else {
        float2 v = make_float2(o[0], o[1]);
        *reinterpret_cast<float2*>(&out[(size_t)gw * C + lane * 2]) = v;
    }
}

// ---------------- min pool --------------------------------------------------
__global__ void min_part_kernel(const float* __restrict__ g) {
    int c = threadIdx.x & 63;
    int r = threadIdx.x >> 6;  // 0..3
    float m = 3.4028235e38f;
    for (int row = blockIdx.x * 4 + r; row < N_NODES; row += gridDim.x * 4)
        m = fminf(m, g[(size_t)row * OUT_CH + c]);
    __shared__ float sm[256];
    sm[threadIdx.x] = m;
    __syncthreads();
    if (threadIdx.x < 128) sm[threadIdx.x] = fminf(sm[threadIdx.x], sm[threadIdx.x + 128]);
    __syncthreads();
    if (threadIdx.x < 64)
        g_partial[blockIdx.x * OUT_CH + threadIdx.x] =
            fminf(sm[threadIdx.x], sm[threadIdx.x + 64]);
}

__global__ void min_final_kernel(float* __restrict__ out) {
    int c = threadIdx.x;  // 64
    float m = 3.4028235e38f;
    for (int b = 0; b < POOL_BLOCKS; b++) m = fminf(m, g_partial[b * OUT_CH + c]);
    out[c] = m;
}

// ---------------- launch ----------------------------------------------------
extern "C" void kernel_launch(void* const* d_in, const int* in_sizes, int n_in,
                              void* d_out, int out_size) {
    const float* x  = (const float*)d_in[0];
    const int*   ei = (const int*)  d_in[1];
    const float* W1 = (const float*)d_in[2];
    const float* b1 = (const float*)d_in[3];
    const float* W2 = (const float*)d_in[4];
    const float* b2 = (const float*)d_in[5];
    const float* W3 = (const float*)d_in[6];
    const float* b3 = (const float*)d_in[7];
    float* out = (float*)d_out;

    __nv_bfloat16* h_ptr = nullptr;
    float* agg_ptr = nullptr;
    cudaGetSymbolAddress((void**)&h_ptr, g_hb);
    cudaGetSymbolAddress((void**)&agg_ptr, g_agg);

    const int SMEM_128 = (128 * 132 + 128 * 132) * 4;  // 135168
    const int SMEM_64  = (128 * 132 + 128 * 68) * 4;   // 102400
    cudaFuncSetAttribute(gemm_mma_kernel<128>,
                         cudaFuncAttributeMaxDynamicSharedMemorySize, SMEM_128);
    cudaFuncSetAttribute(gemm_mma_kernel<64>,
                         cudaFuncAttributeMaxDynamicSharedMemorySize, SMEM_64);

    const int TPB = 256;
    // CSR build
    zero_deg_kernel<<<(N_NODES + TPB - 1) / TPB, TPB>>>();
    count_deg_kernel<<<(N_EDGES + TPB - 1) / TPB, TPB>>>(ei);
    scan_pass1<<<SCAN_NBLK, 256>>>();
    scan_pass2<<<1, 512>>>();
    scan_pass3<<<SCAN_NBLK, 256>>>();
    fill_csr_kernel<<<(N_EDGES + TPB - 1) / TPB, TPB>>>(ei);

    const int gemm_blocks = (N_NODES + 127) / 128;  // 782
    const int spmm_blocks = (N_NODES * 32 + TPB - 1) / TPB;

    // Layer 1
    gemm_mma_kernel<128><<<gemm_blocks, 256, SMEM_128>>>(x, W1, h_ptr, N_NODES);
    spmm_kernel<128, true><<<spmm_blocks, TPB>>>(h_ptr, b1, agg_ptr);

    // Layer 2
    gemm_mma_kernel<128><<<gemm_blocks, 256, SMEM_128>>>(agg_ptr, W2, h_ptr, N_NODES);
    spmm_kernel<128, true><<<spmm_blocks, TPB>>>(h_ptr, b2, agg_ptr);

    // Layer 3 (64 out channels, no relu)
    gemm_mma_kernel<64><<<gemm_blocks, 256, SMEM_64>>>(agg_ptr, W3, h_ptr, N_NODES);
    spmm_kernel<64, false><<<spmm_blocks, TPB>>>(h_ptr, b3, agg_ptr);

    // min pool
    min_part_kernel<<<POOL_BLOCKS, 256>>>(agg_ptr);
    min_final_kernel<<<1, 64>>>(out);
}

// round 7
// speedup vs baseline: 2.1101x; 1.0090x over previous
#include <cuda_runtime.h>
#include <cuda_bf16.h>
#include <math.h>
#include <cstdint>

#define N_NODES 100000
#define N_EDGES 1600000
#define IN_CH   128
#define HID     128
#define OUT_CH  64

#define SCAN_NBLK ((N_NODES + 255) / 256)   // 391

// ---------------- scratch (device globals; no allocation allowed) ----------
__device__ __nv_bfloat16 g_hb[(size_t)N_NODES * HID];  // transformed + src-scaled (bf16)
__device__ float g_agg[(size_t)N_NODES * HID];         // aggregated / activated (fp32)
__device__ float g_dinv[N_NODES];
__device__ int   g_deg[N_NODES];                       // zero at load; re-zeroed each run
__device__ int   g_rowptr[N_NODES + 1];
__device__ int   g_cursor[N_NODES];
__device__ int   g_csr[N_EDGES];
__device__ int   g_bsum[SCAN_NBLK];
__device__ int   g_boff[SCAN_NBLK];
__device__ unsigned int g_min[OUT_CH];                 // float-key min accumulator

// ---------------- float <-> monotone uint key ------------------------------
__device__ __forceinline__ unsigned int fkey(float f) {
    unsigned int u = __float_as_uint(f);
    return (u & 0x80000000u) ? ~u : (u | 0x80000000u);
}
__device__ __forceinline__ float funkey(unsigned int k) {
    unsigned int u = (k & 0x80000000u) ? (k ^ 0x80000000u) : ~k;
    return __uint_as_float(u);
}

// ---------------- CSR build ------------------------------------------------
__global__ void count_deg_kernel(const int* __restrict__ ei) {
    int e4 = (blockIdx.x * blockDim.x + threadIdx.x) * 4;
    if (e4 < N_EDGES) {
        int4 d = *reinterpret_cast<const int4*>(&ei[N_EDGES + e4]);
        atomicAdd(&g_deg[d.x], 1);
        atomicAdd(&g_deg[d.y], 1);
        atomicAdd(&g_deg[d.z], 1);
        atomicAdd(&g_deg[d.w], 1);
    }
}

__global__ void scan_pass1() {
    int i = blockIdx.x * 256 + threadIdx.x;
    int d = (i < N_NODES) ? g_deg[i] : 0;
    __shared__ int sm[256];
    sm[threadIdx.x] = d;
    __syncthreads();
#pragma unroll
    for (int o = 128; o > 0; o >>= 1) {
        if (threadIdx.x < o) sm[threadIdx.x] += sm[threadIdx.x + o];
        __syncthreads();
    }
    if (threadIdx.x == 0) g_bsum[blockIdx.x] = sm[0];
}

__global__ void scan_pass2() {
    __shared__ int sm[512];
    int t = threadIdx.x;
    if (t < OUT_CH) g_min[t] = 0xFFFFFFFFu;   // init fused-pool accumulator
    sm[t] = (t < SCAN_NBLK) ? g_bsum[t] : 0;
    __syncthreads();
    for (int o = 1; o < 512; o <<= 1) {
        int v = (t >= o) ? sm[t - o] : 0;
        __syncthreads();
        sm[t] += v;
        __syncthreads();
    }
    if (t < SCAN_NBLK) g_boff[t] = (t == 0) ? 0 : sm[t - 1];
    if (t == 511) g_rowptr[N_NODES] = sm[SCAN_NBLK - 1];
}

__global__ void scan_pass3() {
    int i = blockIdx.x * 256 + threadIdx.x;
    int d = (i < N_NODES) ? g_deg[i] : 0;
    __shared__ int sm[256];
    int t = threadIdx.x;
    sm[t] = d;
    __syncthreads();
    for (int o = 1; o < 256; o <<= 1) {
        int v = (t >= o) ? sm[t - o] : 0;
        __syncthreads();
        sm[t] += v;
        __syncthreads();
    }
    if (i < N_NODES) {
        int excl = g_boff[blockIdx.x] + sm[t] - d;
        g_rowptr[i] = excl;
        g_cursor[i] = excl;
        g_dinv[i] = rsqrtf((float)(d + 1));  // +1 self-loop
        g_deg[i] = 0;                        // restore zero invariant for next run
    }
}

__global__ void fill_csr_kernel(const int* __restrict__ ei) {
    int e4 = (blockIdx.x * blockDim.x + threadIdx.x) * 4;
    if (e4 < N_EDGES) {
        int4 s = *reinterpret_cast<const int4*>(&ei[e4]);
        int4 d = *reinterpret_cast<const int4*>(&ei[N_EDGES + e4]);
        g_csr[atomicAdd(&g_cursor[d.x], 1)] = s.x;
        g_csr[atomicAdd(&g_cursor[d.y], 1)] = s.y;
        g_csr[atomicAdd(&g_cursor[d.z], 1)] = s.z;
        g_csr[atomicAdd(&g_cursor[d.w], 1)] = s.w;
    }
}

// ---------------- tf32 mma helpers ------------------------------------------
__device__ __forceinline__ uint32_t f2tf32(float f) {
    uint32_t u;
    asm("cvt.rna.tf32.f32 %0, %1;" : "=r"(u) : "f"(f));
    return u;
}

__device__ __forceinline__ void mma_tf32(float* c, const uint32_t* a, const uint32_t* b) {
    asm volatile(
        "mma.sync.aligned.m16n8k8.row.col.f32.tf32.tf32.f32 "
        "{%0,%1,%2,%3}, {%4,%5,%6,%7}, {%8,%9}, {%0,%1,%2,%3};"
        : "+f"(c[0]), "+f"(c[1]), "+f"(c[2]), "+f"(c[3])
        : "r"(a[0]), "r"(a[1]), "r"(a[2]), "r"(a[3]), "r"(b[0]), "r"(b[1]));
}

// ---------------- tensor-core GEMM: outh[m][n] = bf16(dinv[m]*(A@W)[m][n]) --
template <int BN>
__global__ void __launch_bounds__(256)
gemm_mma_kernel(const float* __restrict__ A, const float* __restrict__ W,
                __nv_bfloat16* __restrict__ outh, int M) {
    constexpr int PAD_A = 132;
    constexpr int PAD_B = BN + 4;
    constexpr int TN = BN / 16;

    extern __shared__ uint32_t smem[];
    uint32_t* As = smem;                    // [128][PAD_A]
    uint32_t* Bs = smem + 128 * PAD_A;      // [128][PAD_B]

    const int tid = threadIdx.x;
    const int lane = tid & 31;
    const int wid = tid >> 5;
    const int wm = (wid & 3) * 32;
    const int wn = (wid >> 2) * (BN / 2);
    const int m0 = blockIdx.x * 128;

#pragma unroll
    for (int i = tid; i < 128 * 32; i += 256) {
        int r = i >> 5;
        int c4 = (i & 31) * 4;
        int row = m0 + r;
        float4 v = make_float4(0.f, 0.f, 0.f, 0.f);
        if (row < M)
            v = *reinterpret_cast<const float4*>(&A[(size_t)row * 128 + c4]);
        uint4 u;
        u.x = f2tf32(v.x); u.y = f2tf32(v.y); u.z = f2tf32(v.z); u.w = f2tf32(v.w);
        *reinterpret_cast<uint4*>(&As[r * PAD_A + c4]) = u;
    }
#pragma unroll
    for (int i = tid; i < 128 * (BN / 4); i += 256) {
        int r = i / (BN / 4);
        int c4 = (i % (BN / 4)) * 4;
        float4 v = *reinterpret_cast<const float4*>(&W[(size_t)r * BN + c4]);
        uint4 u;
        u.x = f2tf32(v.x); u.y = f2tf32(v.y); u.z = f2tf32(v.z); u.w = f2tf32(v.w);
        *reinterpret_cast<uint4*>(&Bs[r * PAD_B + c4]) = u;
    }
    __syncthreads();

    float acc[2][TN][4];
#pragma unroll
    for (int mi = 0; mi < 2; mi++)
#pragma unroll
        for (int ni = 0; ni < TN; ni++)
#pragma unroll
            for (int j = 0; j < 4; j++) acc[mi][ni][j] = 0.f;

    const int ar = lane >> 2;
    const int ak = lane & 3;
    const int bn = wn + (lane >> 2);

#pragma unroll
    for (int k0 = 0; k0 < 128; k0 += 8) {
        uint32_t a[2][4];
#pragma unroll
        for (int mi = 0; mi < 2; mi++) {
            int r = wm + mi * 16 + ar;
            a[mi][0] = As[r * PAD_A + k0 + ak];
            a[mi][1] = As[(r + 8) * PAD_A + k0 + ak];
            a[mi][2] = As[r * PAD_A + k0 + ak + 4];
            a[mi][3] = As[(r + 8) * PAD_A + k0 + ak + 4];
        }
        uint32_t b[TN][2];
#pragma unroll
        for (int ni = 0; ni < TN; ni++) {
            b[ni][0] = Bs[(k0 + ak) * PAD_B + bn + ni * 8];
            b[ni][1] = Bs[(k0 + ak + 4) * PAD_B + bn + ni * 8];
        }
#pragma unroll
        for (int mi = 0; mi < 2; mi++)
#pragma unroll
            for (int ni = 0; ni < TN; ni++)
                mma_tf32(acc[mi][ni], a[mi], b[ni]);
    }

#pragma unroll
    for (int mi = 0; mi < 2; mi++) {
        int r0 = m0 + wm + mi * 16 + (lane >> 2);
        int r1 = r0 + 8;
        float d0 = (r0 < M) ? g_dinv[r0] : 0.f;
        float d1 = (r1 < M) ? g_dinv[r1] : 0.f;
#pragma unroll
        for (int ni = 0; ni < TN; ni++) {
            int col = wn + ni * 8 + (lane & 3) * 2;
            if (r0 < M) {
                __nv_bfloat162 v0 =
                    __floats2bfloat162_rn(acc[mi][ni][0] * d0, acc[mi][ni][1] * d0);
                *reinterpret_cast<__nv_bfloat162*>(&outh[(size_t)r0 * BN + col]) = v0;
            }
            if (r1 < M) {
                __nv_bfloat162 v1 =
                    __floats2bfloat162_rn(acc[mi][ni][2] * d1, acc[mi][ni][3] * d1);
                *reinterpret_cast<__nv_bfloat162*>(&outh[(size_t)r1 * BN + col]) = v1;
            }
        }
    }
}

// ---------------- SpMM row aggregation core (bf16 gather, fp32 acc) ---------
template <int C>
__device__ __forceinline__ void spmm_row(const __nv_bfloat16* __restrict__ h,
                                         int node, int lane, float2* acc) {
    constexpr int V = C / 32;
    constexpr int P = V / 2;
    int beg = g_rowptr[node];
    int end = g_rowptr[node + 1];

    // self loop
    {
        const __nv_bfloat162* hp =
            reinterpret_cast<const __nv_bfloat162*>(&h[(size_t)node * C + lane * V]);
#pragma unroll
        for (int p = 0; p < P; p++) acc[p] = __bfloat1622float2(hp[p]);
    }

    int j = beg;
    for (; j + 7 < end; j += 8) {
        const __nv_bfloat162* ptr[8];
#pragma unroll
        for (int q = 0; q < 8; q++) {
            int s = g_csr[j + q];
            ptr[q] = reinterpret_cast<const __nv_bfloat162*>(&h[(size_t)s * C + lane * V]);
        }
#pragma unroll
        for (int p = 0; p < P; p++) {
            float2 v0 = __bfloat1622float2(ptr[0][p]);
            float2 v1 = __bfloat1622float2(ptr[1][p]);
            float2 v2 = __bfloat1622float2(ptr[2][p]);
            float2 v3 = __bfloat1622float2(ptr[3][p]);
            float2 v4 = __bfloat1622float2(ptr[4][p]);
            float2 v5 = __bfloat1622float2(ptr[5][p]);
            float2 v6 = __bfloat1622float2(ptr[6][p]);
            float2 v7 = __bfloat1622float2(ptr[7][p]);
            acc[p].x += ((v0.x + v1.x) + (v2.x + v3.x)) + ((v4.x + v5.x) + (v6.x + v7.x));
            acc[p].y += ((v0.y + v1.y) + (v2.y + v3.y)) + ((v4.y + v5.y) + (v6.y + v7.y));
        }
    }
    for (; j + 3 < end; j += 4) {
        const __nv_bfloat162* ptr[4];
#pragma unroll
        for (int q = 0; q < 4; q++) {
            int s = g_csr[j + q];
            ptr[q] = reinterpret_cast<const __nv_bfloat162*>(&h[(size_t)s * C + lane * V]);
        }
#pragma unroll
        for (int p = 0; p < P; p++) {
            float2 v0 = __bfloat1622float2(ptr[0][p]);
            float2 v1 = __bfloat1622float2(ptr[1][p]);
            float2 v2 = __bfloat1622float2(ptr[2][p]);
            float2 v3 = __bfloat1622float2(ptr[3][p]);
            acc[p].x += (v0.x + v1.x) + (v2.x + v3.x);
            acc[p].y += (v0.y + v1.y) + (v2.y + v3.y);
        }
    }
    for (; j < end; j++) {
        int s = g_csr[j];
        const __nv_bfloat162* p0 =
            reinterpret_cast<const __nv_bfloat162*>(&h[(size_t)s * C + lane * V]);
#pragma unroll
        for (int p = 0; p < P; p++) {
            float2 v0 = __bfloat1622float2(p0[p]);
            acc[p].x += v0.x;
            acc[p].y += v0.y;
        }
    }
}

// ---------------- SpMM (warp per dst node) -> fp32 out, relu ----------------
template <int C>
__global__ void spmm_kernel(const __nv_bfloat16* __restrict__ h,
                            const float* __restrict__ bias,
                            float* __restrict__ out) {
    constexpr int V = C / 32;
    constexpr int P = V / 2;
    int gw = (blockIdx.x * blockDim.x + threadIdx.x) >> 5;
    int lane = threadIdx.x & 31;
    if (gw >= N_NODES) return;

    float2 acc[P];
    spmm_row<C>(h, gw, lane, acc);

    float d = g_dinv[gw];
    float o[V];
#pragma unroll
    for (int p = 0; p < P; p++) {
        float vx = acc[p].x * d + bias[lane * V + p * 2];
        float vy = acc[p].y * d + bias[lane * V + p * 2 + 1];
        o[p * 2] = fmaxf(vx, 0.f);
        o[p * 2 + 1] = fmaxf(vy, 0.f);
    }
    if (V == 4) {
        float4 v = make_float4(o[0], o[1], o[2], o[3]);
        *reinterpret_cast<float4*>(&out[(size_t)gw * C + lane * 4]) = v;
    } else {
        float2 v = make_float2(o[0], o[1]);
        *reinterpret_cast<float2*>(&out[(size_t)gw * C + lane * 2]) = v;
    }
}

// ---------------- SpMM layer-3 fused with min pool (C=64, no relu) ----------
__global__ void spmm_pool_kernel(const __nv_bfloat16* __restrict__ h,
                                 const float* __restrict__ bias) {
    constexpr int C = OUT_CH;   // 64, V=2, P=1
    __shared__ float spool[8 * 64];

    int wlocal = threadIdx.x >> 5;
    int gw = (blockIdx.x * blockDim.x + threadIdx.x) >> 5;
    int lane = threadIdx.x & 31;

    float2 o = make_float2(3.4028235e38f, 3.4028235e38f);
    if (gw < N_NODES) {
        float2 acc[1];
        spmm_row<C>(h, gw, lane, acc);
        float d = g_dinv[gw];
        o.x = acc[0].x * d + bias[lane * 2];
        o.y = acc[0].y * d + bias[lane * 2 + 1];
    }
    spool[wlocal * 64 + lane * 2] = o.x;
    spool[wlocal * 64 + lane * 2 + 1] = o.y;
    __syncthreads();

    if (threadIdx.x < 64) {
        float m = spool[threadIdx.x];
#pragma unroll
        for (int w = 1; w < 8; w++) m = fminf(m, spool[w * 64 + threadIdx.x]);
        atomicMin(&g_min[threadIdx.x], fkey(m));
    }
}

__global__ void min_final_kernel(float* __restrict__ out) {
    int c = threadIdx.x;  // 64
    out[c] = funkey(g_min[c]);
}

// ---------------- launch ----------------------------------------------------
extern "C" void kernel_launch(void* const* d_in, const int* in_sizes, int n_in,
                              void* d_out, int out_size) {
    const float* x  = (const float*)d_in[0];
    const int*   ei = (const int*)  d_in[1];
    const float* W1 = (const float*)d_in[2];
    const float* b1 = (const float*)d_in[3];
    const float* W2 = (const float*)d_in[4];
    const float* b2 = (const float*)d_in[5];
    const float* W3 = (const float*)d_in[6];
    const float* b3 = (const float*)d_in[7];
    float* out = (float*)d_out;

    __nv_bfloat16* h_ptr = nullptr;
    float* agg_ptr = nullptr;
    cudaGetSymbolAddress((void**)&h_ptr, g_hb);
    cudaGetSymbolAddress((void**)&agg_ptr, g_agg);

    const int SMEM_128 = (128 * 132 + 128 * 132) * 4;  // 135168
    const int SMEM_64  = (128 * 132 + 128 * 68) * 4;   // 102400
    cudaFuncSetAttribute(gemm_mma_kernel<128>,
                         cudaFuncAttributeMaxDynamicSharedMemorySize, SMEM_128);
    cudaFuncSetAttribute(gemm_mma_kernel<64>,
                         cudaFuncAttributeMaxDynamicSharedMemorySize, SMEM_64);

    const int TPB = 256;
    // CSR build (g_deg is zero: BSS-initialized at load, re-zeroed in scan_pass3)
    count_deg_kernel<<<(N_EDGES / 4 + TPB - 1) / TPB, TPB>>>(ei);
    scan_pass1<<<SCAN_NBLK, 256>>>();
    scan_pass2<<<1, 512>>>();
    scan_pass3<<<SCAN_NBLK, 256>>>();
    fill_csr_kernel<<<(N_EDGES / 4 + TPB - 1) / TPB, TPB>>>(ei);

    const int gemm_blocks = (N_NODES + 127) / 128;  // 782
    const int spmm_blocks = (N_NODES * 32 + TPB - 1) / TPB;

    // Layer 1
    gemm_mma_kernel<128><<<gemm_blocks, 256, SMEM_128>>>(x, W1, h_ptr, N_NODES);
    spmm_kernel<128><<<spmm_blocks, TPB>>>(h_ptr, b1, agg_ptr);

    // Layer 2
    gemm_mma_kernel<128><<<gemm_blocks, 256, SMEM_128>>>(agg_ptr, W2, h_ptr, N_NODES);
    spmm_kernel<128><<<spmm_blocks, TPB>>>(h_ptr, b2, agg_ptr);

    // Layer 3 (64 out channels, no relu) fused with min pool
    gemm_mma_kernel<64><<<gemm_blocks, 256, SMEM_64>>>(agg_ptr, W3, h_ptr, N_NODES);
    spmm_pool_kernel<<<spmm_blocks, TPB>>>(h_ptr, b3);

    min_final_kernel<<<1, 64>>>(out);
}

// round 8
// speedup vs baseline: 2.1497x; 1.0188x over previous
#include <cuda_runtime.h>
#include <cuda_bf16.h>
#include <math.h>
#include <cstdint>

#define N_NODES 100000
#define N_EDGES 1600000
#define IN_CH   128
#define HID     128
#define OUT_CH  64

#define SCAN_NBLK ((N_NODES + 255) / 256)   // 391

// ---------------- scratch (device globals; no allocation allowed) ----------
__device__ __nv_bfloat16 g_hb[(size_t)N_NODES * HID];  // transformed + src-scaled (bf16)
__device__ float g_agg[(size_t)N_NODES * HID];         // aggregated / activated (fp32)
__device__ float g_dinv[N_NODES];
__device__ int   g_deg[N_NODES];                       // zero at load; re-zeroed each run
__device__ int   g_rowptr[N_NODES + 1];
__device__ int   g_cursor[N_NODES];
__device__ int   g_csr[N_EDGES];
__device__ int   g_bsum[SCAN_NBLK];
__device__ int   g_boff[SCAN_NBLK];
__device__ unsigned int g_min[OUT_CH];                 // float-key min accumulator

// ---------------- float <-> monotone uint key ------------------------------
__device__ __forceinline__ unsigned int fkey(float f) {
    unsigned int u = __float_as_uint(f);
    return (u & 0x80000000u) ? ~u : (u | 0x80000000u);
}
__device__ __forceinline__ float funkey(unsigned int k) {
    unsigned int u = (k & 0x80000000u) ? (k ^ 0x80000000u) : ~k;
    return __uint_as_float(u);
}

// unpack 8 bf16 (uint4) -> 8 floats
__device__ __forceinline__ void unpack8(uint4 v, float* f) {
    float2 t;
    t = __bfloat1622float2(*reinterpret_cast<__nv_bfloat162*>(&v.x)); f[0] = t.x; f[1] = t.y;
    t = __bfloat1622float2(*reinterpret_cast<__nv_bfloat162*>(&v.y)); f[2] = t.x; f[3] = t.y;
    t = __bfloat1622float2(*reinterpret_cast<__nv_bfloat162*>(&v.z)); f[4] = t.x; f[5] = t.y;
    t = __bfloat1622float2(*reinterpret_cast<__nv_bfloat162*>(&v.w)); f[6] = t.x; f[7] = t.y;
}

// ---------------- CSR build ------------------------------------------------
__global__ void count_deg_kernel(const int* __restrict__ ei) {
    int e4 = (blockIdx.x * blockDim.x + threadIdx.x) * 4;
    if (e4 < N_EDGES) {
        int4 d = *reinterpret_cast<const int4*>(&ei[N_EDGES + e4]);
        atomicAdd(&g_deg[d.x], 1);
        atomicAdd(&g_deg[d.y], 1);
        atomicAdd(&g_deg[d.z], 1);
        atomicAdd(&g_deg[d.w], 1);
    }
}

__global__ void scan_pass1() {
    int i = blockIdx.x * 256 + threadIdx.x;
    int d = (i < N_NODES) ? g_deg[i] : 0;
    __shared__ int sm[256];
    sm[threadIdx.x] = d;
    __syncthreads();
#pragma unroll
    for (int o = 128; o > 0; o >>= 1) {
        if (threadIdx.x < o) sm[threadIdx.x] += sm[threadIdx.x + o];
        __syncthreads();
    }
    if (threadIdx.x == 0) g_bsum[blockIdx.x] = sm[0];
}

__global__ void scan_pass2() {
    __shared__ int sm[512];
    int t = threadIdx.x;
    if (t < OUT_CH) g_min[t] = 0xFFFFFFFFu;   // init fused-pool accumulator
    sm[t] = (t < SCAN_NBLK) ? g_bsum[t] : 0;
    __syncthreads();
    for (int o = 1; o < 512; o <<= 1) {
        int v = (t >= o) ? sm[t - o] : 0;
        __syncthreads();
        sm[t] += v;
        __syncthreads();
    }
    if (t < SCAN_NBLK) g_boff[t] = (t == 0) ? 0 : sm[t - 1];
    if (t == 511) g_rowptr[N_NODES] = sm[SCAN_NBLK - 1];
}

__global__ void scan_pass3() {
    int i = blockIdx.x * 256 + threadIdx.x;
    int d = (i < N_NODES) ? g_deg[i] : 0;
    __shared__ int sm[256];
    int t = threadIdx.x;
    sm[t] = d;
    __syncthreads();
    for (int o = 1; o < 256; o <<= 1) {
        int v = (t >= o) ? sm[t - o] : 0;
        __syncthreads();
        sm[t] += v;
        __syncthreads();
    }
    if (i < N_NODES) {
        int excl = g_boff[blockIdx.x] + sm[t] - d;
        g_rowptr[i] = excl;
        g_cursor[i] = excl;
        g_dinv[i] = rsqrtf((float)(d + 1));  // +1 self-loop
        g_deg[i] = 0;                        // restore zero invariant for next run
    }
}

__global__ void fill_csr_kernel(const int* __restrict__ ei) {
    int e4 = (blockIdx.x * blockDim.x + threadIdx.x) * 4;
    if (e4 < N_EDGES) {
        int4 s = *reinterpret_cast<const int4*>(&ei[e4]);
        int4 d = *reinterpret_cast<const int4*>(&ei[N_EDGES + e4]);
        g_csr[atomicAdd(&g_cursor[d.x], 1)] = s.x;
        g_csr[atomicAdd(&g_cursor[d.y], 1)] = s.y;
        g_csr[atomicAdd(&g_cursor[d.z], 1)] = s.z;
        g_csr[atomicAdd(&g_cursor[d.w], 1)] = s.w;
    }
}

// ---------------- tf32 mma helpers ------------------------------------------
__device__ __forceinline__ uint32_t f2tf32(float f) {
    uint32_t u;
    asm("cvt.rna.tf32.f32 %0, %1;" : "=r"(u) : "f"(f));
    return u;
}

__device__ __forceinline__ void mma_tf32(float* c, const uint32_t* a, const uint32_t* b) {
    asm volatile(
        "mma.sync.aligned.m16n8k8.row.col.f32.tf32.tf32.f32 "
        "{%0,%1,%2,%3}, {%4,%5,%6,%7}, {%8,%9}, {%0,%1,%2,%3};"
        : "+f"(c[0]), "+f"(c[1]), "+f"(c[2]), "+f"(c[3])
        : "r"(a[0]), "r"(a[1]), "r"(a[2]), "r"(a[3]), "r"(b[0]), "r"(b[1]));
}

// ---------------- tensor-core GEMM: outh[m][n] = bf16(dinv[m]*(A@W)[m][n]) --
template <int BN>
__global__ void __launch_bounds__(256)
gemm_mma_kernel(const float* __restrict__ A, const float* __restrict__ W,
                __nv_bfloat16* __restrict__ outh, int M) {
    constexpr int PAD_A = 132;
    constexpr int PAD_B = BN + 4;
    constexpr int TN = BN / 16;

    extern __shared__ uint32_t smem[];
    uint32_t* As = smem;                    // [128][PAD_A]
    uint32_t* Bs = smem + 128 * PAD_A;      // [128][PAD_B]

    const int tid = threadIdx.x;
    const int lane = tid & 31;
    const int wid = tid >> 5;
    const int wm = (wid & 3) * 32;
    const int wn = (wid >> 2) * (BN / 2);
    const int m0 = blockIdx.x * 128;

#pragma unroll
    for (int i = tid; i < 128 * 32; i += 256) {
        int r = i >> 5;
        int c4 = (i & 31) * 4;
        int row = m0 + r;
        float4 v = make_float4(0.f, 0.f, 0.f, 0.f);
        if (row < M)
            v = *reinterpret_cast<const float4*>(&A[(size_t)row * 128 + c4]);
        uint4 u;
        u.x = f2tf32(v.x); u.y = f2tf32(v.y); u.z = f2tf32(v.z); u.w = f2tf32(v.w);
        *reinterpret_cast<uint4*>(&As[r * PAD_A + c4]) = u;
    }
#pragma unroll
    for (int i = tid; i < 128 * (BN / 4); i += 256) {
        int r = i / (BN / 4);
        int c4 = (i % (BN / 4)) * 4;
        float4 v = *reinterpret_cast<const float4*>(&W[(size_t)r * BN + c4]);
        uint4 u;
        u.x = f2tf32(v.x); u.y = f2tf32(v.y); u.z = f2tf32(v.z); u.w = f2tf32(v.w);
        *reinterpret_cast<uint4*>(&Bs[r * PAD_B + c4]) = u;
    }
    __syncthreads();

    float acc[2][TN][4];
#pragma unroll
    for (int mi = 0; mi < 2; mi++)
#pragma unroll
        for (int ni = 0; ni < TN; ni++)
#pragma unroll
            for (int j = 0; j < 4; j++) acc[mi][ni][j] = 0.f;

    const int ar = lane >> 2;
    const int ak = lane & 3;
    const int bn = wn + (lane >> 2);

#pragma unroll
    for (int k0 = 0; k0 < 128; k0 += 8) {
        uint32_t a[2][4];
#pragma unroll
        for (int mi = 0; mi < 2; mi++) {
            int r = wm + mi * 16 + ar;
            a[mi][0] = As[r * PAD_A + k0 + ak];
            a[mi][1] = As[(r + 8) * PAD_A + k0 + ak];
            a[mi][2] = As[r * PAD_A + k0 + ak + 4];
            a[mi][3] = As[(r + 8) * PAD_A + k0 + ak + 4];
        }
        uint32_t b[TN][2];
#pragma unroll
        for (int ni = 0; ni < TN; ni++) {
            b[ni][0] = Bs[(k0 + ak) * PAD_B + bn + ni * 8];
            b[ni][1] = Bs[(k0 + ak + 4) * PAD_B + bn + ni * 8];
        }
#pragma unroll
        for (int mi = 0; mi < 2; mi++)
#pragma unroll
            for (int ni = 0; ni < TN; ni++)
                mma_tf32(acc[mi][ni], a[mi], b[ni]);
    }

#pragma unroll
    for (int mi = 0; mi < 2; mi++) {
        int r0 = m0 + wm + mi * 16 + (lane >> 2);
        int r1 = r0 + 8;
        float d0 = (r0 < M) ? g_dinv[r0] : 0.f;
        float d1 = (r1 < M) ? g_dinv[r1] : 0.f;
#pragma unroll
        for (int ni = 0; ni < TN; ni++) {
            int col = wn + ni * 8 + (lane & 3) * 2;
            if (r0 < M) {
                __nv_bfloat162 v0 =
                    __floats2bfloat162_rn(acc[mi][ni][0] * d0, acc[mi][ni][1] * d0);
                *reinterpret_cast<__nv_bfloat162*>(&outh[(size_t)r0 * BN + col]) = v0;
            }
            if (r1 < M) {
                __nv_bfloat162 v1 =
                    __floats2bfloat162_rn(acc[mi][ni][2] * d1, acc[mi][ni][3] * d1);
                *reinterpret_cast<__nv_bfloat162*>(&outh[(size_t)r1 * BN + col]) = v1;
            }
        }
    }
}

// ---------------- SpMM C=128: warp per node, 2 edges in parallel ------------
// Each half-warp (16 lanes x uint4 = 256B) gathers one edge row.
__global__ void spmm128_kernel(const __nv_bfloat16* __restrict__ h,
                               const float* __restrict__ bias,
                               float* __restrict__ out) {
    int gw = (blockIdx.x * blockDim.x + threadIdx.x) >> 5;
    int lane = threadIdx.x & 31;
    if (gw >= N_NODES) return;
    const int half = lane >> 4;
    const int hl = lane & 15;

    int beg = g_rowptr[gw];
    int end = g_rowptr[gw + 1];

    float acc[8];
    if (half == 0) {  // self loop on half 0
        uint4 v = *reinterpret_cast<const uint4*>(&h[(size_t)gw * 128 + hl * 8]);
        unpack8(v, acc);
    } else {
#pragma unroll
        for (int i = 0; i < 8; i++) acc[i] = 0.f;
    }

    int j = beg + half;
    for (; j + 2 < end; j += 4) {   // 2 edges per half in flight
        int s0 = g_csr[j];
        int s1 = g_csr[j + 2];
        uint4 v0 = *reinterpret_cast<const uint4*>(&h[(size_t)s0 * 128 + hl * 8]);
        uint4 v1 = *reinterpret_cast<const uint4*>(&h[(size_t)s1 * 128 + hl * 8]);
        float f0[8], f1[8];
        unpack8(v0, f0);
        unpack8(v1, f1);
#pragma unroll
        for (int i = 0; i < 8; i++) acc[i] += f0[i] + f1[i];
    }
    if (j < end) {
        int s0 = g_csr[j];
        uint4 v0 = *reinterpret_cast<const uint4*>(&h[(size_t)s0 * 128 + hl * 8]);
        float f0[8];
        unpack8(v0, f0);
#pragma unroll
        for (int i = 0; i < 8; i++) acc[i] += f0[i];
    }

    // combine halves
#pragma unroll
    for (int i = 0; i < 8; i++) acc[i] += __shfl_xor_sync(0xFFFFFFFFu, acc[i], 16);

    float d = g_dinv[gw];
    float o[8];
#pragma unroll
    for (int i = 0; i < 8; i++)
        o[i] = fmaxf(acc[i] * d + bias[hl * 8 + i], 0.f);

    // lanes 0-15 store first float4 of their 8-ch slice, lanes 16-31 the second
    float4 v = (half == 0) ? make_float4(o[0], o[1], o[2], o[3])
                           : make_float4(o[4], o[5], o[6], o[7]);
    *reinterpret_cast<float4*>(&out[(size_t)gw * 128 + hl * 8 + half * 4]) = v;
}

// ---------------- SpMM C=64 fused with min pool: 4 edges in parallel --------
// Each quarter-warp (8 lanes x uint4 = 128B) gathers one edge row.
__global__ void spmm_pool_kernel(const __nv_bfloat16* __restrict__ h,
                                 const float* __restrict__ bias) {
    __shared__ float spool[8 * 64];

    int wlocal = threadIdx.x >> 5;
    int gw = (blockIdx.x * blockDim.x + threadIdx.x) >> 5;
    int lane = threadIdx.x & 31;
    const int quarter = lane >> 3;
    const int ql = lane & 7;

    float o[8];
    if (gw < N_NODES) {
        int beg = g_rowptr[gw];
        int end = g_rowptr[gw + 1];

        float acc[8];
        if (quarter == 0) {  // self loop on quarter 0
            uint4 v = *reinterpret_cast<const uint4*>(&h[(size_t)gw * 64 + ql * 8]);
            unpack8(v, acc);
        } else {
#pragma unroll
            for (int i = 0; i < 8; i++) acc[i] = 0.f;
        }

        int j = beg + quarter;
        for (; j + 4 < end; j += 8) {   // 2 edges per quarter in flight
            int s0 = g_csr[j];
            int s1 = g_csr[j + 4];
            uint4 v0 = *reinterpret_cast<const uint4*>(&h[(size_t)s0 * 64 + ql * 8]);
            uint4 v1 = *reinterpret_cast<const uint4*>(&h[(size_t)s1 * 64 + ql * 8]);
            float f0[8], f1[8];
            unpack8(v0, f0);
            unpack8(v1, f1);
#pragma unroll
            for (int i = 0; i < 8; i++) acc[i] += f0[i] + f1[i];
        }
        if (j < end) {
            int s0 = g_csr[j];
            uint4 v0 = *reinterpret_cast<const uint4*>(&h[(size_t)s0 * 64 + ql * 8]);
            float f0[8];
            unpack8(v0, f0);
#pragma unroll
            for (int i = 0; i < 8; i++) acc[i] += f0[i];
        }

        // combine quarters
#pragma unroll
        for (int i = 0; i < 8; i++) acc[i] += __shfl_xor_sync(0xFFFFFFFFu, acc[i], 8);
#pragma unroll
        for (int i = 0; i < 8; i++) acc[i] += __shfl_xor_sync(0xFFFFFFFFu, acc[i], 16);

        float d = g_dinv[gw];
#pragma unroll
        for (int i = 0; i < 8; i++) o[i] = acc[i] * d + bias[ql * 8 + i];
    } else {
#pragma unroll
        for (int i = 0; i < 8; i++) o[i] = 3.4028235e38f;
    }

    if (lane < 8) {
#pragma unroll
        for (int i = 0; i < 8; i++) spool[wlocal * 64 + ql * 8 + i] = o[i];
    }
    __syncthreads();

    if (threadIdx.x < 64) {
        float m = spool[threadIdx.x];
#pragma unroll
        for (int w = 1; w < 8; w++) m = fminf(m, spool[w * 64 + threadIdx.x]);
        atomicMin(&g_min[threadIdx.x], fkey(m));
    }
}

__global__ void min_final_kernel(float* __restrict__ out) {
    int c = threadIdx.x;  // 64
    out[c] = funkey(g_min[c]);
}

// ---------------- launch ----------------------------------------------------
extern "C" void kernel_launch(void* const* d_in, const int* in_sizes, int n_in,
                              void* d_out, int out_size) {
    const float* x  = (const float*)d_in[0];
    const int*   ei = (const int*)  d_in[1];
    const float* W1 = (const float*)d_in[2];
    const float* b1 = (const float*)d_in[3];
    const float* W2 = (const float*)d_in[4];
    const float* b2 = (const float*)d_in[5];
    const float* W3 = (const float*)d_in[6];
    const float* b3 = (const float*)d_in[7];
    float* out = (float*)d_out;

    __nv_bfloat16* h_ptr = nullptr;
    float* agg_ptr = nullptr;
    cudaGetSymbolAddress((void**)&h_ptr, g_hb);
    cudaGetSymbolAddress((void**)&agg_ptr, g_agg);

    const int SMEM_128 = (128 * 132 + 128 * 132) * 4;  // 135168
    const int SMEM_64  = (128 * 132 + 128 * 68) * 4;   // 102400
    cudaFuncSetAttribute(gemm_mma_kernel<128>,
                         cudaFuncAttributeMaxDynamicSharedMemorySize, SMEM_128);
    cudaFuncSetAttribute(gemm_mma_kernel<64>,
                         cudaFuncAttributeMaxDynamicSharedMemorySize, SMEM_64);

    const int TPB = 256;
    // CSR build (g_deg is zero: BSS-initialized at load, re-zeroed in scan_pass3)
    count_deg_kernel<<<(N_EDGES / 4 + TPB - 1) / TPB, TPB>>>(ei);
    scan_pass1<<<SCAN_NBLK, 256>>>();
    scan_pass2<<<1, 512>>>();
    scan_pass3<<<SCAN_NBLK, 256>>>();
    fill_csr_kernel<<<(N_EDGES / 4 + TPB - 1) / TPB, TPB>>>(ei);

    const int gemm_blocks = (N_NODES + 127) / 128;  // 782
    const int spmm_blocks = (N_NODES * 32 + TPB - 1) / TPB;

    // Layer 1
    gemm_mma_kernel<128><<<gemm_blocks, 256, SMEM_128>>>(x, W1, h_ptr, N_NODES);
    spmm128_kernel<<<spmm_blocks, TPB>>>(h_ptr, b1, agg_ptr);

    // Layer 2
    gemm_mma_kernel<128><<<gemm_blocks, 256, SMEM_128>>>(agg_ptr, W2, h_ptr, N_NODES);
    spmm128_kernel<<<spmm_blocks, TPB>>>(h_ptr, b2, agg_ptr);

    // Layer 3 (64 out channels, no relu) fused with min pool
    gemm_mma_kernel<64><<<gemm_blocks, 256, SMEM_64>>>(agg_ptr, W3, h_ptr, N_NODES);
    spmm_pool_kernel<<<spmm_blocks, TPB>>>(h_ptr, b3);

    min_final_kernel<<<1, 64>>>(out);
}